// round 16
// baseline (speedup 1.0000x reference)
#include <cuda_runtime.h>
#include <math.h>

#define BB 4
#define DD 32
#define HH 512
#define WW 512
#define HWP (HH * WW)
#define KK 16
#define DELTA_A 0.1f
#define DELTA_R 1.0f
#define ALPHA 1.0f
#define BETA 1.0f
#define GAMMA 0.001f

#define TPB 256
#define PXT 4                     // pixels per thread (float4)
#define BPX (TPB * PXT)           // 1024 pixels per tile
#define NBLK (HWP / BPX)          // 256 tiles per image
#define GRIDX 148                 // persistent CTAs per image row
#define NCTA_TOT (GRIDX * BB)     // 592 CTAs = one wave at 4 CTAs/SM

#define ESTRIDE 36                // Esh row stride in floats (144B, float4-aligned)

// Zero-initialized statics; poller resets counters each run so CUDA-graph
// replays stay deterministic. Partials/g_rep/g_reg fully overwritten per run.
__device__ float g_part_att[BB][NBLK][KK];
__device__ float g_part_cnt[BB][NBLK][KK];
__device__ float g_rep[BB];
__device__ float g_reg[BB];
__device__ unsigned int g_work[BB];   // tile work counters
__device__ unsigned int g_done;       // CTA completion counter

__global__ __launch_bounds__(TPB) void main_kernel(
    const float* __restrict__ emb,
    const int* __restrict__ target,
    const int* __restrict__ centers,
    float* __restrict__ res)
{
    __shared__ float Esh[17 * ESTRIDE];  // padded rows; row 16 = dummy zeros
    __shared__ float En2[17];
    __shared__ int   lab[KK];
    __shared__ float w_att[8][17];
    __shared__ float w_cnt[8][17];
    __shared__ float v_sh[KK * KK];      // side-block pairs; epilogue staging
    __shared__ float att_k[BB][KK];      // epilogue only
    __shared__ float cnt_k[BB][KK];
    __shared__ int   sh_tile;

    const int b    = blockIdx.y;
    const int tid  = threadIdx.x;
    const int wid  = tid >> 5;
    const int lane = tid & 31;

    const int embBase = b * (DD * HWP);   // 32-bit safe (<2^31)
    const float* embb = emb + embBase;

    // ---- per-CTA prologue (once, amortized over ~1.73 tiles) ----
    for (int idx = tid; idx < KK * DD; idx += TPB) {
        int k = idx / DD, d = idx % DD;
        int cy = centers[(b * KK + k) * 2 + 0];
        int cx = centers[(b * KK + k) * 2 + 1];
        Esh[k * ESTRIDE + d] = emb[embBase + d * HWP + cy * WW + cx];
    }
    for (int idx = tid; idx < ESTRIDE; idx += TPB) Esh[16 * ESTRIDE + idx] = 0.0f;
    if (tid < KK) {
        int cy = centers[(b * KK + tid) * 2 + 0];
        int cx = centers[(b * KK + tid) * 2 + 1];
        lab[tid] = target[b * HWP + cy * WW + cx];
    }
    __syncthreads();
    if (tid < KK) {
        // n2: eager-XLA order — individually ROUNDED squares, SEQUENTIAL adds
        float s = 0.0f;
        #pragma unroll
        for (int d = 0; d < DD; d++) {
            float e = Esh[tid * ESTRIDE + d];
            s = __fadd_rn(s, __fmul_rn(e, e));
        }
        En2[tid] = s;
    }
    if (tid == 16) En2[16] = 0.0f;
    __syncthreads();

    // ---- rep/reg side-computation: 4 CTAs (x==0), bit-exact reference path ----
    if (blockIdx.x == 0) {
        {
            int i = tid >> 4, j = tid & 15;
            float dot = 0.0f;
            #pragma unroll
            for (int d = 0; d < DD; d++) {
                dot = __fmaf_rn(Esh[i * ESTRIDE + d], Esh[j * ESTRIDE + d], dot);
            }
            float s   = __fadd_rn(En2[i], En2[j]);
            float t   = __fmul_rn(2.0f, dot);
            float d2  = __fadd_rn(s, -t);
            float nrm = (d2 > 0.0f) ? sqrtf(d2) : 0.0f;   // _safe_sqrt(relu(d2))
            v_sh[i * KK + j] = fmaxf(__fadd_rn(DELTA_R, -nrm), 0.0f);
        }
        __syncthreads();
        if (tid == 0) {
            float s = 0.0f;
            #pragma unroll 4
            for (int m = 0; m < KK * KK; m++) s = __fadd_rn(s, v_sh[m]);
            g_rep[b] = __fadd_rn(s, -(float)KK * DELTA_R);
        } else if (tid == 1) {
            float sg = 0.0f;
            #pragma unroll 4
            for (int k = 0; k < KK; k++) {
                float t = En2[k];
                sg = __fadd_rn(sg, (t > 0.0f) ? sqrtf(t) : 0.0f);
            }
            g_reg[b] = sg;
        }
    }

    const float4* EshF = reinterpret_cast<const float4*>(Esh);

    // ---- persistent work-stealing over tiles ----
    for (;;) {
        if (tid == 0) sh_tile = (int)atomicAdd(&g_work[b], 1u);
        // zero per-warp accumulators while waiting on the counter
        for (int idx = tid; idx < 8 * 17; idx += TPB) {
            w_att[idx / 17][idx % 17] = 0.0f;
            w_cnt[idx / 17][idx % 17] = 0.0f;
        }
        __syncthreads();
        const int tile = sh_tile;
        if (tile >= NBLK) break;

        const int p0 = tile * BPX + tid * PXT;

        const int4 t4 = *reinterpret_cast<const int4*>(target + b * HWP + p0);

        unsigned mA = 0, mB = 0, mC = 0, mD = 0;
        #pragma unroll
        for (int k = 0; k < KK; k++) {
            int lk = lab[k];
            unsigned bit = 1u << k;
            if (lk == t4.x) mA |= bit;
            if (lk == t4.y) mB |= bit;
            if (lk == t4.z) mC |= bit;
            if (lk == t4.w) mD |= bit;
        }
        int kA = mA ? (__ffs(mA) - 1) : 16;
        int kB = mB ? (__ffs(mB) - 1) : 16;
        int kC = mC ? (__ffs(mC) - 1) : 16;
        int kD = mD ? (__ffs(mD) - 1) : 16;

        const float4* xp = reinterpret_cast<const float4*>(embb) + (p0 >> 2);
        const int rA = kA * (ESTRIDE / 4), rB = kB * (ESTRIDE / 4);
        const int rC = kC * (ESTRIDE / 4), rD = kD * (ESTRIDE / 4);

        float xnA = 0.f, xnB = 0.f, xnC = 0.f, xnD = 0.f;
        float dA  = 0.f, dB  = 0.f, dC  = 0.f, dD  = 0.f;

        #pragma unroll
        for (int d4 = 0; d4 < DD / 4; d4++) {
            float4 eA = EshF[rA + d4];
            float4 eB = EshF[rB + d4];
            float4 eC = EshF[rC + d4];
            float4 eD = EshF[rD + d4];
            const float* ea = reinterpret_cast<const float*>(&eA);
            const float* eb = reinterpret_cast<const float*>(&eB);
            const float* ec = reinterpret_cast<const float*>(&eC);
            const float* ed = reinterpret_cast<const float*>(&eD);
            #pragma unroll
            for (int j = 0; j < 4; j++) {
                float4 x = xp[(d4 * 4 + j) * (HWP / 4)];
                xnA = fmaf(x.x, x.x, xnA);
                xnB = fmaf(x.y, x.y, xnB);
                xnC = fmaf(x.z, x.z, xnC);
                xnD = fmaf(x.w, x.w, xnD);
                dA = fmaf(ea[j], x.x, dA);
                dB = fmaf(eb[j], x.y, dB);
                dC = fmaf(ec[j], x.z, dC);
                dD = fmaf(ed[j], x.w, dD);
            }
        }

        float vA, vB, vC, vD;
        {
            float d2, nrm;
            d2 = (En2[kA] + xnA) - 2.0f * dA; nrm = (d2 > 0.f) ? sqrtf(d2) : 0.f;
            vA = (kA < 16) ? fmaxf(nrm - DELTA_A, 0.f) : 0.f;
            d2 = (En2[kB] + xnB) - 2.0f * dB; nrm = (d2 > 0.f) ? sqrtf(d2) : 0.f;
            vB = (kB < 16) ? fmaxf(nrm - DELTA_A, 0.f) : 0.f;
            d2 = (En2[kC] + xnC) - 2.0f * dC; nrm = (d2 > 0.f) ? sqrtf(d2) : 0.f;
            vC = (kC < 16) ? fmaxf(nrm - DELTA_A, 0.f) : 0.f;
            d2 = (En2[kD] + xnD) - 2.0f * dD; nrm = (d2 > 0.f) ? sqrtf(d2) : 0.f;
            vD = (kD < 16) ? fmaxf(nrm - DELTA_A, 0.f) : 0.f;
        }

        float* att_row = w_att[wid];
        float* cnt_row = w_cnt[wid];
        #pragma unroll
        for (int s = 0; s < 4; s++) {
            int   k = (s == 0) ? kA : (s == 1) ? kB : (s == 2) ? kC : kD;
            float v = (s == 0) ? vA : (s == 1) ? vB : (s == 2) ? vC : vD;
            int k0 = __shfl_sync(0xFFFFFFFFu, k, 0);
            bool uni = __all_sync(0xFFFFFFFFu, k == k0);
            if (uni) {
                float sum = v;
                #pragma unroll
                for (int off = 16; off > 0; off >>= 1)
                    sum += __shfl_down_sync(0xFFFFFFFFu, sum, off);
                if (lane == 0 && k0 < 16) {
                    att_row[k0] += sum;
                    cnt_row[k0] += 32.0f;
                }
            } else {
                if (k < 16) {
                    atomicAdd(&att_row[k], v);
                    atomicAdd(&cnt_row[k], 1.0f);
                }
            }
        }

        // Rare slow path: extra matching centers beyond the first
        unsigned exA = mA & (mA - 1), exB = mB & (mB - 1);
        unsigned exC = mC & (mC - 1), exD = mD & (mD - 1);
        if (exA | exB | exC | exD) {
            #pragma unroll
            for (int s = 0; s < 4; s++) {
                unsigned ex = (s == 0) ? exA : (s == 1) ? exB : (s == 2) ? exC : exD;
                float xn    = (s == 0) ? xnA : (s == 1) ? xnB : (s == 2) ? xnC : xnD;
                int p = p0 + s;
                while (ex) {
                    int k = __ffs(ex) - 1;
                    ex &= ex - 1;
                    float dot = 0.0f;
                    for (int d = 0; d < DD; d++)
                        dot = fmaf(Esh[k * ESTRIDE + d], embb[d * HWP + p], dot);
                    float d2  = (En2[k] + xn) - 2.0f * dot;
                    float nrm = (d2 > 0.f) ? sqrtf(d2) : 0.f;
                    atomicAdd(&att_row[k], fmaxf(nrm - DELTA_A, 0.f));
                    atomicAdd(&cnt_row[k], 1.0f);
                }
            }
        }

        __syncthreads();
        // Per-tile partials via plain STG (writers are warp 0)
        if (tid < KK) {
            float sa = 0.f, sc = 0.f;
            #pragma unroll
            for (int w = 0; w < 8; w++) { sa += w_att[w][tid]; sc += w_cnt[w][tid]; }
            g_part_att[b][tile][tid] = sa;
            g_part_cnt[b][tile][tid] = sc;
        }
        __syncthreads();
    }

    // Release: warp 0 fences its stores (partials + g_rep/g_reg + g_work
    // atomics), then tid 0 signals with a return-unused atomic (REDG).
    if (tid < 32) __threadfence();
    __syncthreads();
    if (tid == 0) atomicAdd(&g_done, 1u);

    // ---- poller CTA runs the epilogue ----
    const bool poller = (blockIdx.x == GRIDX - 1) && (blockIdx.y == BB - 1);
    if (!poller) return;

    if (tid == 0) {
        unsigned v;
        do {
            __nanosleep(200);
            asm volatile("ld.acquire.gpu.global.u32 %0, [%1];"
                         : "=r"(v) : "l"(&g_done) : "memory");
        } while (v < (unsigned)NCTA_TOT);
        // all CTAs done -> safe to reset counters for the next graph replay
        g_done = 0;
        #pragma unroll
        for (int bb = 0; bb < BB; bb++) g_work[bb] = 0;
    }
    __syncthreads();

    // ---- epilogue: reduce partials (hot in L2), att divides, final scan ----
    {
        int g = tid >> 2, sub = tid & 3;
        int bb = g >> 4, k = g & 15;
        float sa = 0.f, sc = 0.f;
        #pragma unroll 4
        for (int i = sub; i < NBLK; i += 4) {
            sa += g_part_att[bb][i][k];
            sc += g_part_cnt[bb][i][k];
        }
        v_sh[tid] = sa;    // red_att staging (256)
        Esh[tid]  = sc;    // red_cnt staging (reuse, 612 >= 256)
    }
    __syncthreads();

    if (tid < 64) {
        int bb = tid >> 4, k = tid & 15;
        att_k[bb][k] = v_sh[tid * 4] + v_sh[tid * 4 + 1] + v_sh[tid * 4 + 2] + v_sh[tid * 4 + 3];
        cnt_k[bb][k] = Esh[tid * 4]  + Esh[tid * 4 + 1]  + Esh[tid * 4 + 2]  + Esh[tid * 4 + 3];
    }
    __syncthreads();

    if (tid < BB) {
        float sa = 0.0f;
        #pragma unroll
        for (int k = 0; k < KK; k++) {
            float cnt = cnt_k[tid][k];
            float denom = fmaxf(cnt - 1.0f, 1.0f);
            sa += att_k[tid][k] / denom;
        }
        v_sh[tid] = sa;    // att staging
    }
    __syncthreads();

    if (tid == 0) {
        const float div_att = (float)KK;
        const float div_rep = (float)(KK * (KK - 1));
        const float div_reg = (float)KK;
        float att = 0.0f, rep = 0.0f, reg = 0.0f;
        #pragma unroll
        for (int bb = 0; bb < BB; bb++) {
            att = __fdiv_rn(__fadd_rn(att, v_sh[bb]), div_att);
            rep = __fdiv_rn(__fadd_rn(rep, g_rep[bb]), div_rep);
            reg = __fdiv_rn(__fadd_rn(reg, g_reg[bb]), div_reg);
        }
        float loss = __fadd_rn(__fadd_rn(__fmul_rn(ALPHA, att), __fmul_rn(BETA, rep)),
                               __fmul_rn(GAMMA, reg));
        res[0] = loss;
        res[1] = att;
        res[2] = rep;
    }
}

extern "C" void kernel_launch(void* const* d_in, const int* in_sizes, int n_in,
                              void* d_out, int out_size) {
    const float* emb     = (const float*)d_in[0];
    const int*   target  = (const int*)d_in[1];
    const int*   centers = (const int*)d_in[2];
    float* res = (float*)d_out;

    dim3 grid(GRIDX, BB, 1);
    main_kernel<<<grid, TPB>>>(emb, target, centers, res);
}

// round 17
// speedup vs baseline: 1.1550x; 1.1550x over previous
#include <cuda_runtime.h>
#include <math.h>

#define BB 4
#define DD 32
#define HH 512
#define WW 512
#define HWP (HH * WW)
#define KK 16
#define DELTA_A 0.1f
#define DELTA_R 1.0f
#define ALPHA 1.0f
#define BETA 1.0f
#define GAMMA 0.001f

#define TPB 256
#define PXT 4                     // pixels per thread (float4)
#define NBLK (HWP / (TPB * PXT))  // 256 blocks per image

#define ESTRIDE 36                // Esh row stride in floats (144B, float4-aligned)

// Per-block partials: fully rewritten every run -> no pre-zero, no resets,
// no counters anywhere. Deterministic across graph replays by construction.
__device__ float g_part_att[BB][NBLK][KK];
__device__ float g_part_cnt[BB][NBLK][KK];
__device__ float g_rep[BB];      // overwritten every run by x==0 blocks
__device__ float g_reg[BB];

__global__ __launch_bounds__(TPB) void main_kernel(
    const float* __restrict__ emb,
    const int* __restrict__ target,
    const int* __restrict__ centers)
{
    __shared__ float Esh[17 * ESTRIDE];  // padded rows; row 16 = dummy zeros
    __shared__ float En2[17];
    __shared__ int   lab[KK];
    __shared__ float w_att[8][17];
    __shared__ float w_cnt[8][17];
    __shared__ float v_sh[KK * KK];      // side-block pairs only

    const int b    = blockIdx.y;
    const int tid  = threadIdx.x;
    const int wid  = tid >> 5;
    const int lane = tid & 31;

    const int embBase = b * (DD * HWP);   // 32-bit safe (<2^31)
    const float* embb = emb + embBase;

    // Load center embeddings into padded shared
    for (int idx = tid; idx < KK * DD; idx += TPB) {
        int k = idx / DD, d = idx % DD;
        int cy = centers[(b * KK + k) * 2 + 0];
        int cx = centers[(b * KK + k) * 2 + 1];
        Esh[k * ESTRIDE + d] = emb[embBase + d * HWP + cy * WW + cx];
    }
    for (int idx = tid; idx < ESTRIDE; idx += TPB) Esh[16 * ESTRIDE + idx] = 0.0f;
    if (tid < KK) {
        int cy = centers[(b * KK + tid) * 2 + 0];
        int cx = centers[(b * KK + tid) * 2 + 1];
        lab[tid] = target[b * HWP + cy * WW + cx];
    }
    for (int idx = tid; idx < 8 * 17; idx += TPB) {
        w_att[idx / 17][idx % 17] = 0.0f;
        w_cnt[idx / 17][idx % 17] = 0.0f;
    }
    __syncthreads();
    if (tid < KK) {
        // n2: eager-XLA order — individually ROUNDED squares, SEQUENTIAL adds
        float s = 0.0f;
        #pragma unroll
        for (int d = 0; d < DD; d++) {
            float e = Esh[tid * ESTRIDE + d];
            s = __fadd_rn(s, __fmul_rn(e, e));
        }
        En2[tid] = s;
    }
    if (tid == 16) En2[16] = 0.0f;
    __syncthreads();

    // ---- rep/reg side-computation on the 4 blocks with x==0 (hidden under
    //      the other 1020). Bit-exact reference path.
    if (blockIdx.x == 0) {
        {
            int i = tid >> 4, j = tid & 15;
            float dot = 0.0f;
            #pragma unroll
            for (int d = 0; d < DD; d++) {
                dot = __fmaf_rn(Esh[i * ESTRIDE + d], Esh[j * ESTRIDE + d], dot);
            }
            float s   = __fadd_rn(En2[i], En2[j]);
            float t   = __fmul_rn(2.0f, dot);
            float d2  = __fadd_rn(s, -t);
            float nrm = (d2 > 0.0f) ? sqrtf(d2) : 0.0f;   // _safe_sqrt(relu(d2))
            v_sh[i * KK + j] = fmaxf(__fadd_rn(DELTA_R, -nrm), 0.0f);
        }
        __syncthreads();
        if (tid == 0) {
            float s = 0.0f;
            #pragma unroll 4
            for (int m = 0; m < KK * KK; m++) s = __fadd_rn(s, v_sh[m]);
            g_rep[b] = __fadd_rn(s, -(float)KK * DELTA_R);
        } else if (tid == 1) {
            float sg = 0.0f;
            #pragma unroll 4
            for (int k = 0; k < KK; k++) {
                float t = En2[k];
                sg = __fadd_rn(sg, (t > 0.0f) ? sqrtf(t) : 0.0f);
            }
            g_reg[b] = sg;
        }
    }

    const int p0 = (blockIdx.x * TPB + tid) * PXT;

    const int4 t4 = *reinterpret_cast<const int4*>(target + b * HWP + p0);

    unsigned mA = 0, mB = 0, mC = 0, mD = 0;
    #pragma unroll
    for (int k = 0; k < KK; k++) {
        int lk = lab[k];
        unsigned bit = 1u << k;
        if (lk == t4.x) mA |= bit;
        if (lk == t4.y) mB |= bit;
        if (lk == t4.z) mC |= bit;
        if (lk == t4.w) mD |= bit;
    }
    int kA = mA ? (__ffs(mA) - 1) : 16;
    int kB = mB ? (__ffs(mB) - 1) : 16;
    int kC = mC ? (__ffs(mC) - 1) : 16;
    int kD = mD ? (__ffs(mD) - 1) : 16;

    const float4* xp   = reinterpret_cast<const float4*>(embb) + (p0 >> 2);
    const float4* EshF = reinterpret_cast<const float4*>(Esh);
    const int rA = kA * (ESTRIDE / 4), rB = kB * (ESTRIDE / 4);
    const int rC = kC * (ESTRIDE / 4), rD = kD * (ESTRIDE / 4);

    float xnA = 0.f, xnB = 0.f, xnC = 0.f, xnD = 0.f;
    float dA  = 0.f, dB  = 0.f, dC  = 0.f, dD  = 0.f;

    #pragma unroll
    for (int d4 = 0; d4 < DD / 4; d4++) {
        float4 eA = EshF[rA + d4];
        float4 eB = EshF[rB + d4];
        float4 eC = EshF[rC + d4];
        float4 eD = EshF[rD + d4];
        const float* ea = reinterpret_cast<const float*>(&eA);
        const float* eb = reinterpret_cast<const float*>(&eB);
        const float* ec = reinterpret_cast<const float*>(&eC);
        const float* ed = reinterpret_cast<const float*>(&eD);
        #pragma unroll
        for (int j = 0; j < 4; j++) {
            float4 x = xp[(d4 * 4 + j) * (HWP / 4)];
            xnA = fmaf(x.x, x.x, xnA);
            xnB = fmaf(x.y, x.y, xnB);
            xnC = fmaf(x.z, x.z, xnC);
            xnD = fmaf(x.w, x.w, xnD);
            dA = fmaf(ea[j], x.x, dA);
            dB = fmaf(eb[j], x.y, dB);
            dC = fmaf(ec[j], x.z, dC);
            dD = fmaf(ed[j], x.w, dD);
        }
    }

    float vA, vB, vC, vD;
    {
        float d2, nrm;
        d2 = (En2[kA] + xnA) - 2.0f * dA; nrm = (d2 > 0.f) ? sqrtf(d2) : 0.f;
        vA = (kA < 16) ? fmaxf(nrm - DELTA_A, 0.f) : 0.f;
        d2 = (En2[kB] + xnB) - 2.0f * dB; nrm = (d2 > 0.f) ? sqrtf(d2) : 0.f;
        vB = (kB < 16) ? fmaxf(nrm - DELTA_A, 0.f) : 0.f;
        d2 = (En2[kC] + xnC) - 2.0f * dC; nrm = (d2 > 0.f) ? sqrtf(d2) : 0.f;
        vC = (kC < 16) ? fmaxf(nrm - DELTA_A, 0.f) : 0.f;
        d2 = (En2[kD] + xnD) - 2.0f * dD; nrm = (d2 > 0.f) ? sqrtf(d2) : 0.f;
        vD = (kD < 16) ? fmaxf(nrm - DELTA_A, 0.f) : 0.f;
    }

    float* att_row = w_att[wid];
    float* cnt_row = w_cnt[wid];
    #pragma unroll
    for (int s = 0; s < 4; s++) {
        int   k = (s == 0) ? kA : (s == 1) ? kB : (s == 2) ? kC : kD;
        float v = (s == 0) ? vA : (s == 1) ? vB : (s == 2) ? vC : vD;
        int k0 = __shfl_sync(0xFFFFFFFFu, k, 0);
        bool uni = __all_sync(0xFFFFFFFFu, k == k0);
        if (uni) {
            float sum = v;
            #pragma unroll
            for (int off = 16; off > 0; off >>= 1)
                sum += __shfl_down_sync(0xFFFFFFFFu, sum, off);
            if (lane == 0 && k0 < 16) {
                att_row[k0] += sum;
                cnt_row[k0] += 32.0f;
            }
        } else {
            if (k < 16) {
                atomicAdd(&att_row[k], v);
                atomicAdd(&cnt_row[k], 1.0f);
            }
        }
    }

    // Rare slow path: extra matching centers beyond the first
    unsigned exA = mA & (mA - 1), exB = mB & (mB - 1);
    unsigned exC = mC & (mC - 1), exD = mD & (mD - 1);
    if (exA | exB | exC | exD) {
        #pragma unroll
        for (int s = 0; s < 4; s++) {
            unsigned ex = (s == 0) ? exA : (s == 1) ? exB : (s == 2) ? exC : exD;
            float xn    = (s == 0) ? xnA : (s == 1) ? xnB : (s == 2) ? xnC : xnD;
            int p = p0 + s;
            while (ex) {
                int k = __ffs(ex) - 1;
                ex &= ex - 1;
                float dot = 0.0f;
                for (int d = 0; d < DD; d++)
                    dot = fmaf(Esh[k * ESTRIDE + d], embb[d * HWP + p], dot);
                float d2  = (En2[k] + xn) - 2.0f * dot;
                float nrm = (d2 > 0.f) ? sqrtf(d2) : 0.f;
                atomicAdd(&att_row[k], fmaxf(nrm - DELTA_A, 0.f));
                atomicAdd(&cnt_row[k], 1.0f);
            }
        }
    }

    __syncthreads();
    // Per-block partials via plain STG (kernel boundary handles visibility)
    if (tid < KK) {
        float sa = 0.f, sc = 0.f;
        #pragma unroll
        for (int w = 0; w < 8; w++) { sa += w_att[w][tid]; sc += w_cnt[w][tid]; }
        g_part_att[b][blockIdx.x][tid] = sa;
        g_part_cnt[b][blockIdx.x][tid] = sc;
    }
}

// Lean post kernel: 1024 threads, one block. Reduces partials (L2-hot),
// att divides, final scan. No emb access, no big unrolled body.
__global__ __launch_bounds__(1024) void finalize_post(float* __restrict__ res)
{
    __shared__ float red_a[64][16];
    __shared__ float red_c[64][16];
    __shared__ float att_k[BB][KK];
    __shared__ float cnt_k[BB][KK];
    __shared__ float s_att_sh[BB];

    const int tid = threadIdx.x;

    // 64 (b,k) pairs x 16 sub-lanes; each sub-lane sums 16 tiles (32 LDGs)
    {
        int g = tid >> 4, sub = tid & 15;
        int bb = g >> 4, k = g & 15;
        float sa = 0.f, sc = 0.f;
        #pragma unroll
        for (int i = sub; i < NBLK; i += 16) {
            sa += g_part_att[bb][i][k];
            sc += g_part_cnt[bb][i][k];
        }
        red_a[g][sub] = sa;
        red_c[g][sub] = sc;
    }
    __syncthreads();

    if (tid < 64) {
        int bb = tid >> 4, k = tid & 15;
        float sa = 0.f, sc = 0.f;
        #pragma unroll
        for (int s = 0; s < 16; s++) { sa += red_a[tid][s]; sc += red_c[tid][s]; }
        att_k[bb][k] = sa;
        cnt_k[bb][k] = sc;
    }
    __syncthreads();

    if (tid < BB) {
        float sa = 0.0f;
        #pragma unroll
        for (int k = 0; k < KK; k++) {
            float cnt = cnt_k[tid][k];
            float denom = fmaxf(cnt - 1.0f, 1.0f);
            sa += att_k[tid][k] / denom;
        }
        s_att_sh[tid] = sa;
    }
    __syncthreads();

    if (tid == 0) {
        const float div_att = (float)KK;
        const float div_rep = (float)(KK * (KK - 1));
        const float div_reg = (float)KK;
        float att = 0.0f, rep = 0.0f, reg = 0.0f;
        #pragma unroll
        for (int bb = 0; bb < BB; bb++) {
            att = __fdiv_rn(__fadd_rn(att, s_att_sh[bb]), div_att);
            rep = __fdiv_rn(__fadd_rn(rep, g_rep[bb]), div_rep);
            reg = __fdiv_rn(__fadd_rn(reg, g_reg[bb]), div_reg);
        }
        float loss = __fadd_rn(__fadd_rn(__fmul_rn(ALPHA, att), __fmul_rn(BETA, rep)),
                               __fmul_rn(GAMMA, reg));
        res[0] = loss;
        res[1] = att;
        res[2] = rep;
    }
}

extern "C" void kernel_launch(void* const* d_in, const int* in_sizes, int n_in,
                              void* d_out, int out_size) {
    const float* emb     = (const float*)d_in[0];
    const int*   target  = (const int*)d_in[1];
    const int*   centers = (const int*)d_in[2];
    float* res = (float*)d_out;

    dim3 grid(NBLK, BB, 1);
    main_kernel<<<grid, TPB>>>(emb, target, centers);

    finalize_post<<<1, 1024>>>(res);
}